// round 6
// baseline (speedup 1.0000x reference)
#include <cuda_runtime.h>

#define MAX_NODES 100000
#define D 128

// Scratch (allocation-free rule: __device__ globals)
__device__ float g_hW[MAX_NODES * D];     // h @ W^T
__device__ float g_Wt[D * D];             // W transposed: Wt[k][j] = W[j][k]
__device__ int   g_row_ptr[MAX_NODES + 1];

// ---------------------------------------------------------------------------
// K0: transpose W (tiny)
// ---------------------------------------------------------------------------
__global__ void k_transpose_W(const float* __restrict__ W) {
    int idx = blockIdx.x * blockDim.x + threadIdx.x;
    if (idx < D * D) {
        int j = idx >> 7;       // row of W
        int k = idx & 127;      // col of W
        g_Wt[k * D + j] = W[j * D + k];
    }
}

// ---------------------------------------------------------------------------
// K0b: build row_ptr from sorted edge_rows in O(E), coalesced, no atomics.
// row_ptr[r] = first edge index with edge_rows >= r (lower_bound semantics).
// Thread i fills the gap between edge i and i+1; every entry written once.
// ---------------------------------------------------------------------------
__global__ void k_rowptr(const int* __restrict__ edge_rows, int N, int E) {
    int i = blockIdx.x * blockDim.x + threadIdx.x;
    if (i >= E) return;
    int r0 = edge_rows[i];
    int r1 = (i + 1 < E) ? edge_rows[i + 1] : N;
    if (i == 0) {
        for (int r = 0; r <= r0; r++) g_row_ptr[r] = 0;
    }
    for (int r = r0 + 1; r <= r1; r++) g_row_ptr[r] = i + 1;
}

// ---------------------------------------------------------------------------
// K1: hW = h @ W^T  (out[i][j] = sum_k h[i][k] * Wt[k][j])
// Block: 64 rows x 128 cols, 256 threads, 8x4 micro-tile per thread.
// Inner product uses packed fp32 FMA (fma.rn.f32x2): 2 MACs per fma-pipe
// slot, IEEE-identical numerics per lane. Wt rows read as coalesced
// LDG.128 (L1-hot, 64KB). h tile staged in smem; per-k reads broadcast LDS.
// ---------------------------------------------------------------------------
__global__ void __launch_bounds__(256) k_gemm_hW(const float* __restrict__ h, int N) {
    __shared__ float hs[64][D];
    int t = threadIdx.x;
    int row0 = blockIdx.x * 64;

#pragma unroll
    for (int i = 0; i < 8; i++) {
        int idx4 = t + i * 256;          // 0..2047 float4 slots
        int r  = idx4 >> 5;              // 0..63
        int c4 = idx4 & 31;              // 0..31
        float4 v = make_float4(0.f, 0.f, 0.f, 0.f);
        int row = row0 + r;
        if (row < N) v = *(const float4*)&h[(long long)row * D + c4 * 4];
        *(float4*)&hs[r][c4 * 4] = v;
    }
    __syncthreads();

    int cg = t & 31;    // column group: cols [4*cg, 4*cg+3]
    int rg = t >> 5;    // row group: rows [8*rg, 8*rg+7]

    // accumulators as packed f32x2 pairs: acc2[r][0] = cols {0,1}, [1] = {2,3}
    unsigned long long acc2[8][2];
#pragma unroll
    for (int r = 0; r < 8; r++) { acc2[r][0] = 0ull; acc2[r][1] = 0ull; }

#pragma unroll 4
    for (int k = 0; k < D; k++) {
        float4 w = *(const float4*)&g_Wt[k * D + cg * 4];
        unsigned long long w01, w23;
        asm("mov.b64 %0, {%1, %2};" : "=l"(w01) : "f"(w.x), "f"(w.y));
        asm("mov.b64 %0, {%1, %2};" : "=l"(w23) : "f"(w.z), "f"(w.w));
#pragma unroll
        for (int r = 0; r < 8; r++) {
            float a = hs[rg * 8 + r][k];
            unsigned long long aa;
            asm("mov.b64 %0, {%1, %1};" : "=l"(aa) : "f"(a));
            asm("fma.rn.f32x2 %0, %1, %2, %0;" : "+l"(acc2[r][0]) : "l"(aa), "l"(w01));
            asm("fma.rn.f32x2 %0, %1, %2, %0;" : "+l"(acc2[r][1]) : "l"(aa), "l"(w23));
        }
    }

#pragma unroll
    for (int r = 0; r < 8; r++) {
        int row = row0 + rg * 8 + r;
        if (row < N) {
            float4 v;
            asm("mov.b64 {%0, %1}, %2;" : "=f"(v.x), "=f"(v.y) : "l"(acc2[r][0]));
            asm("mov.b64 {%0, %1}, %2;" : "=f"(v.z), "=f"(v.w) : "l"(acc2[r][1]));
            *(float4*)&g_hW[(long long)row * D + cg * 4] = v;
        }
    }
}

// ---------------------------------------------------------------------------
// K2: SpMM on hW + bias + relu  ->  d_out
// One warp per output row (exclusive ownership, no atomics). Row bounds from
// precomputed g_row_ptr (L2 hits). Each lane owns 4 consecutive features
// (float4). Edge loop unrolled x8: 8 independent col->gather chains in
// flight per iteration to hide DRAM(col stream) + L2(gather) latency.
// Edge streams use __ldcs (evict-first) so the once-read 26MB edge data
// does not displace the L2-resident 51MB hW gather working set.
// ---------------------------------------------------------------------------
__global__ void __launch_bounds__(256) k_spmm(
    const int*   __restrict__ edge_cols,
    const float* __restrict__ edge_vals,
    const float* __restrict__ bias,
    float*       __restrict__ out,
    int N)
{
    __shared__ int bounds[9];
    int t = threadIdx.x;
    int base = blockIdx.x * 8;

    if (t < 9) {
        int target = base + t;
        bounds[t] = g_row_ptr[target > N ? N : target];
    }
    __syncthreads();

    int w    = t >> 5;   // warp id 0..7
    int lane = t & 31;
    int row  = base + w;
    if (row >= N) return;

    int s = bounds[w];
    int e = bounds[w + 1];
    int lo = lane * 4;

    float4 acc = make_float4(0.f, 0.f, 0.f, 0.f);

    int i = s;
    // unroll-8 main loop: 8 independent 16B gather chains in flight
    for (; i + 7 < e; i += 8) {
        int c[8]; float v[8];
#pragma unroll
        for (int u = 0; u < 8; u++) c[u] = __ldcs(&edge_cols[i + u]);
#pragma unroll
        for (int u = 0; u < 8; u++) v[u] = __ldcs(&edge_vals[i + u]);
        float4 g[8];
#pragma unroll
        for (int u = 0; u < 8; u++) g[u] = *(const float4*)&g_hW[c[u] * D + lo];
#pragma unroll
        for (int u = 0; u < 8; u++) {
            acc.x += v[u] * g[u].x;
            acc.y += v[u] * g[u].y;
            acc.z += v[u] * g[u].z;
            acc.w += v[u] * g[u].w;
        }
    }
    // remainder, 4-wide then scalar
    for (; i + 3 < e; i += 4) {
        int   c0 = __ldcs(&edge_cols[i]);
        int   c1 = __ldcs(&edge_cols[i + 1]);
        int   c2 = __ldcs(&edge_cols[i + 2]);
        int   c3 = __ldcs(&edge_cols[i + 3]);
        float v0 = __ldcs(&edge_vals[i]);
        float v1 = __ldcs(&edge_vals[i + 1]);
        float v2 = __ldcs(&edge_vals[i + 2]);
        float v3 = __ldcs(&edge_vals[i + 3]);
        float4 h0 = *(const float4*)&g_hW[c0 * D + lo];
        float4 h1 = *(const float4*)&g_hW[c1 * D + lo];
        float4 h2 = *(const float4*)&g_hW[c2 * D + lo];
        float4 h3 = *(const float4*)&g_hW[c3 * D + lo];
        acc.x += v0 * h0.x; acc.y += v0 * h0.y; acc.z += v0 * h0.z; acc.w += v0 * h0.w;
        acc.x += v1 * h1.x; acc.y += v1 * h1.y; acc.z += v1 * h1.z; acc.w += v1 * h1.w;
        acc.x += v2 * h2.x; acc.y += v2 * h2.y; acc.z += v2 * h2.z; acc.w += v2 * h2.w;
        acc.x += v3 * h3.x; acc.y += v3 * h3.y; acc.z += v3 * h3.z; acc.w += v3 * h3.w;
    }
    for (; i < e; i++) {
        int   c  = __ldcs(&edge_cols[i]);
        float vv = __ldcs(&edge_vals[i]);
        float4 hv = *(const float4*)&g_hW[c * D + lo];
        acc.x += vv * hv.x; acc.y += vv * hv.y; acc.z += vv * hv.z; acc.w += vv * hv.w;
    }

    // bias is 512B, L1-hot after first warp; loading here (not hoisted) frees
    // 4 registers across the unroll-8 loop window.
    float bx = __ldg(&bias[lo]);
    float by = __ldg(&bias[lo + 1]);
    float bz = __ldg(&bias[lo + 2]);
    float bw = __ldg(&bias[lo + 3]);
    float4 r;
    r.x = fmaxf(acc.x + bx, 0.f);
    r.y = fmaxf(acc.y + by, 0.f);
    r.z = fmaxf(acc.z + bz, 0.f);
    r.w = fmaxf(acc.w + bw, 0.f);
    *(float4*)&out[(long long)row * D + lo] = r;
}

// ---------------------------------------------------------------------------
// Launch
// Inputs (metadata order): edge_rows[i32 E], edge_cols[i32 E], edge_vals[f32 E],
//                          h[f32 N*128], W[f32 128*128], b[f32 128]
// Output: f32 N*128
// ---------------------------------------------------------------------------
extern "C" void kernel_launch(void* const* d_in, const int* in_sizes, int n_in,
                              void* d_out, int out_size) {
    const int*   edge_rows = (const int*)d_in[0];
    const int*   edge_cols = (const int*)d_in[1];
    const float* edge_vals = (const float*)d_in[2];
    const float* h         = (const float*)d_in[3];
    const float* W         = (const float*)d_in[4];
    const float* b         = (const float*)d_in[5];
    float*       out       = (float*)d_out;

    int E = in_sizes[0];
    int N = in_sizes[3] / D;

    k_transpose_W<<<(D * D + 255) / 256, 256>>>(W);
    k_rowptr<<<(E + 255) / 256, 256>>>(edge_rows, N, E);
    k_gemm_hW<<<(N + 63) / 64, 256>>>(h, N);
    k_spmm<<<(N + 7) / 8, 256>>>(edge_cols, edge_vals, b, out, N);
}

// round 7
// speedup vs baseline: 1.0435x; 1.0435x over previous
#include <cuda_runtime.h>
#include <cuda_fp16.h>

#define MAX_NODES 100000
#define D 128

// Scratch (allocation-free rule: __device__ globals)
__device__ __half g_hW[MAX_NODES * D];    // h @ W^T, stored fp16 (halves gather traffic)
__device__ float  g_Wt[D * D];            // W transposed: Wt[k][j] = W[j][k]
__device__ int    g_row_ptr[MAX_NODES + 1];

// ---------------------------------------------------------------------------
// K0: transpose W (tiny)
// ---------------------------------------------------------------------------
__global__ void k_transpose_W(const float* __restrict__ W) {
    int idx = blockIdx.x * blockDim.x + threadIdx.x;
    if (idx < D * D) {
        int j = idx >> 7;       // row of W
        int k = idx & 127;      // col of W
        g_Wt[k * D + j] = W[j * D + k];
    }
}

// ---------------------------------------------------------------------------
// K0b: build row_ptr from sorted edge_rows in O(E), coalesced, no atomics.
// ---------------------------------------------------------------------------
__global__ void k_rowptr(const int* __restrict__ edge_rows, int N, int E) {
    int i = blockIdx.x * blockDim.x + threadIdx.x;
    if (i >= E) return;
    int r0 = edge_rows[i];
    int r1 = (i + 1 < E) ? edge_rows[i + 1] : N;
    if (i == 0) {
        for (int r = 0; r <= r0; r++) g_row_ptr[r] = 0;
    }
    for (int r = r0 + 1; r <= r1; r++) g_row_ptr[r] = i + 1;
}

// ---------------------------------------------------------------------------
// K1: hW = h @ W^T  (fp32 compute via packed fma.rn.f32x2; fp16 store).
// Block: 64 rows x 128 cols, 256 threads, 8x4 micro-tile per thread.
// ---------------------------------------------------------------------------
__global__ void __launch_bounds__(256) k_gemm_hW(const float* __restrict__ h, int N) {
    __shared__ float hs[64][D];
    int t = threadIdx.x;
    int row0 = blockIdx.x * 64;

#pragma unroll
    for (int i = 0; i < 8; i++) {
        int idx4 = t + i * 256;          // 0..2047 float4 slots
        int r  = idx4 >> 5;              // 0..63
        int c4 = idx4 & 31;              // 0..31
        float4 v = make_float4(0.f, 0.f, 0.f, 0.f);
        int row = row0 + r;
        if (row < N) v = *(const float4*)&h[(long long)row * D + c4 * 4];
        *(float4*)&hs[r][c4 * 4] = v;
    }
    __syncthreads();

    int cg = t & 31;    // column group: cols [4*cg, 4*cg+3]
    int rg = t >> 5;    // row group: rows [8*rg, 8*rg+7]

    // accumulators as packed f32x2 pairs: acc2[r][0] = cols {0,1}, [1] = {2,3}
    unsigned long long acc2[8][2];
#pragma unroll
    for (int r = 0; r < 8; r++) { acc2[r][0] = 0ull; acc2[r][1] = 0ull; }

#pragma unroll 4
    for (int k = 0; k < D; k++) {
        float4 w = *(const float4*)&g_Wt[k * D + cg * 4];
        unsigned long long w01, w23;
        asm("mov.b64 %0, {%1, %2};" : "=l"(w01) : "f"(w.x), "f"(w.y));
        asm("mov.b64 %0, {%1, %2};" : "=l"(w23) : "f"(w.z), "f"(w.w));
#pragma unroll
        for (int r = 0; r < 8; r++) {
            float a = hs[rg * 8 + r][k];
            unsigned long long aa;
            asm("mov.b64 %0, {%1, %1};" : "=l"(aa) : "f"(a));
            asm("fma.rn.f32x2 %0, %1, %2, %0;" : "+l"(acc2[r][0]) : "l"(aa), "l"(w01));
            asm("fma.rn.f32x2 %0, %1, %2, %0;" : "+l"(acc2[r][1]) : "l"(aa), "l"(w23));
        }
    }

#pragma unroll
    for (int r = 0; r < 8; r++) {
        int row = row0 + rg * 8 + r;
        if (row < N) {
            float4 v;
            asm("mov.b64 {%0, %1}, %2;" : "=f"(v.x), "=f"(v.y) : "l"(acc2[r][0]));
            asm("mov.b64 {%0, %1}, %2;" : "=f"(v.z), "=f"(v.w) : "l"(acc2[r][1]));
            __half2 p01 = __floats2half2_rn(v.x, v.y);
            __half2 p23 = __floats2half2_rn(v.z, v.w);
            uint2 u;
            u.x = *reinterpret_cast<unsigned*>(&p01);
            u.y = *reinterpret_cast<unsigned*>(&p23);
            *(uint2*)&g_hW[(long long)row * D + cg * 4] = u;   // 8B store, coalesced
        }
    }
}

// ---------------------------------------------------------------------------
// K2: SpMM on fp16 hW + bias + relu -> d_out (fp32).
// Persistent warps: one wave (592 blocks = 4/SM), each warp strides rows.
// Exclusive row ownership, no atomics, no smem, no syncthreads. Each lane
// owns 4 features: 8B fp16 gather (2 L1 lines/warp vs 4 at fp32). Edge
// streams via __ldcs (evict-first) protect hW's L2 residency. Unroll x8 for
// 8 independent col->gather chains in flight.
// ---------------------------------------------------------------------------
__global__ void __launch_bounds__(256, 4) k_spmm(
    const int*   __restrict__ edge_cols,
    const float* __restrict__ edge_vals,
    const float* __restrict__ bias,
    float*       __restrict__ out,
    int N)
{
    int lane = threadIdx.x & 31;
    int gw   = (blockIdx.x * blockDim.x + threadIdx.x) >> 5;
    int nw   = (gridDim.x * blockDim.x) >> 5;
    int lo   = lane * 4;

    float bx = __ldg(&bias[lo]);
    float by = __ldg(&bias[lo + 1]);
    float bz = __ldg(&bias[lo + 2]);
    float bw = __ldg(&bias[lo + 3]);

    for (int row = gw; row < N; row += nw) {
        int s = __ldg(&g_row_ptr[row]);
        int e = __ldg(&g_row_ptr[row + 1]);

        float4 acc = make_float4(0.f, 0.f, 0.f, 0.f);

        int i = s;
        for (; i + 7 < e; i += 8) {
            int c[8]; float v[8];
#pragma unroll
            for (int u = 0; u < 8; u++) c[u] = __ldcs(&edge_cols[i + u]);
#pragma unroll
            for (int u = 0; u < 8; u++) v[u] = __ldcs(&edge_vals[i + u]);
            uint2 g[8];
#pragma unroll
            for (int u = 0; u < 8; u++)
                g[u] = *(const uint2*)&g_hW[(long long)c[u] * D + lo];
#pragma unroll
            for (int u = 0; u < 8; u++) {
                __half2 ha = *reinterpret_cast<__half2*>(&g[u].x);
                __half2 hb = *reinterpret_cast<__half2*>(&g[u].y);
                float2 fa = __half22float2(ha);
                float2 fb = __half22float2(hb);
                acc.x = fmaf(v[u], fa.x, acc.x);
                acc.y = fmaf(v[u], fa.y, acc.y);
                acc.z = fmaf(v[u], fb.x, acc.z);
                acc.w = fmaf(v[u], fb.y, acc.w);
            }
        }
        for (; i < e; i++) {
            int   c  = __ldcs(&edge_cols[i]);
            float vv = __ldcs(&edge_vals[i]);
            uint2 gg = *(const uint2*)&g_hW[(long long)c * D + lo];
            __half2 ha = *reinterpret_cast<__half2*>(&gg.x);
            __half2 hb = *reinterpret_cast<__half2*>(&gg.y);
            float2 fa = __half22float2(ha);
            float2 fb = __half22float2(hb);
            acc.x = fmaf(vv, fa.x, acc.x);
            acc.y = fmaf(vv, fa.y, acc.y);
            acc.z = fmaf(vv, fb.x, acc.z);
            acc.w = fmaf(vv, fb.y, acc.w);
        }

        float4 r;
        r.x = fmaxf(acc.x + bx, 0.f);
        r.y = fmaxf(acc.y + by, 0.f);
        r.z = fmaxf(acc.z + bz, 0.f);
        r.w = fmaxf(acc.w + bw, 0.f);
        *(float4*)&out[(long long)row * D + lo] = r;
    }
}

// ---------------------------------------------------------------------------
// Launch
// Inputs (metadata order): edge_rows[i32 E], edge_cols[i32 E], edge_vals[f32 E],
//                          h[f32 N*128], W[f32 128*128], b[f32 128]
// Output: f32 N*128
// ---------------------------------------------------------------------------
extern "C" void kernel_launch(void* const* d_in, const int* in_sizes, int n_in,
                              void* d_out, int out_size) {
    const int*   edge_rows = (const int*)d_in[0];
    const int*   edge_cols = (const int*)d_in[1];
    const float* edge_vals = (const float*)d_in[2];
    const float* h         = (const float*)d_in[3];
    const float* W         = (const float*)d_in[4];
    const float* b         = (const float*)d_in[5];
    float*       out       = (float*)d_out;

    int E = in_sizes[0];
    int N = in_sizes[3] / D;

    k_transpose_W<<<(D * D + 255) / 256, 256>>>(W);
    k_rowptr<<<(E + 255) / 256, 256>>>(edge_rows, N, E);
    k_gemm_hW<<<(N + 63) / 64, 256>>>(h, N);
    k_spmm<<<592, 256>>>(edge_cols, edge_vals, b, out, N);   // one wave, 4 blocks/SM
}

// round 11
// speedup vs baseline: 1.1607x; 1.1123x over previous
#include <cuda_runtime.h>
#include <cuda_fp16.h>

#define MAX_NODES 100000
#define D 128

// Scratch (allocation-free rule: __device__ globals)
__device__ __half g_hW[MAX_NODES * D];    // h @ W^T, stored fp16 (halves gather traffic)
__device__ float  g_Wt[D * D];            // W transposed: Wt[k][j] = W[j][k]
__device__ int    g_row_ptr[MAX_NODES + 1];

// ---------------------------------------------------------------------------
// K0: transpose W (tiny)
// ---------------------------------------------------------------------------
__global__ void k_transpose_W(const float* __restrict__ W) {
    int idx = blockIdx.x * blockDim.x + threadIdx.x;
    if (idx < D * D) {
        int j = idx >> 7;       // row of W
        int k = idx & 127;      // col of W
        g_Wt[k * D + j] = W[j * D + k];
    }
}

// ---------------------------------------------------------------------------
// K0b: build row_ptr from sorted edge_rows in O(E), coalesced, no atomics.
// ---------------------------------------------------------------------------
__global__ void k_rowptr(const int* __restrict__ edge_rows, int N, int E) {
    int i = blockIdx.x * blockDim.x + threadIdx.x;
    if (i >= E) return;
    int r0 = edge_rows[i];
    int r1 = (i + 1 < E) ? edge_rows[i + 1] : N;
    if (i == 0) {
        for (int r = 0; r <= r0; r++) g_row_ptr[r] = 0;
    }
    for (int r = r0 + 1; r <= r1; r++) g_row_ptr[r] = i + 1;
}

// ---------------------------------------------------------------------------
// K1: hW = h @ W^T  (fp32 compute via packed fma.rn.f32x2; fp16 store).
// Block: 64 rows x 128 cols, 256 threads, 8x4 micro-tile per thread.
// ---------------------------------------------------------------------------
__global__ void __launch_bounds__(256) k_gemm_hW(const float* __restrict__ h, int N) {
    __shared__ float hs[64][D];
    int t = threadIdx.x;
    int row0 = blockIdx.x * 64;

#pragma unroll
    for (int i = 0; i < 8; i++) {
        int idx4 = t + i * 256;          // 0..2047 float4 slots
        int r  = idx4 >> 5;              // 0..63
        int c4 = idx4 & 31;              // 0..31
        float4 v = make_float4(0.f, 0.f, 0.f, 0.f);
        int row = row0 + r;
        if (row < N) v = *(const float4*)&h[(long long)row * D + c4 * 4];
        *(float4*)&hs[r][c4 * 4] = v;
    }
    __syncthreads();

    int cg = t & 31;    // column group: cols [4*cg, 4*cg+3]
    int rg = t >> 5;    // row group: rows [8*rg, 8*rg+7]

    unsigned long long acc2[8][2];
#pragma unroll
    for (int r = 0; r < 8; r++) { acc2[r][0] = 0ull; acc2[r][1] = 0ull; }

#pragma unroll 4
    for (int k = 0; k < D; k++) {
        float4 w = *(const float4*)&g_Wt[k * D + cg * 4];
        unsigned long long w01, w23;
        asm("mov.b64 %0, {%1, %2};" : "=l"(w01) : "f"(w.x), "f"(w.y));
        asm("mov.b64 %0, {%1, %2};" : "=l"(w23) : "f"(w.z), "f"(w.w));
#pragma unroll
        for (int r = 0; r < 8; r++) {
            float a = hs[rg * 8 + r][k];
            unsigned long long aa;
            asm("mov.b64 %0, {%1, %1};" : "=l"(aa) : "f"(a));
            asm("fma.rn.f32x2 %0, %1, %2, %0;" : "+l"(acc2[r][0]) : "l"(aa), "l"(w01));
            asm("fma.rn.f32x2 %0, %1, %2, %0;" : "+l"(acc2[r][1]) : "l"(aa), "l"(w23));
        }
    }

#pragma unroll
    for (int r = 0; r < 8; r++) {
        int row = row0 + rg * 8 + r;
        if (row < N) {
            float4 v;
            asm("mov.b64 {%0, %1}, %2;" : "=f"(v.x), "=f"(v.y) : "l"(acc2[r][0]));
            asm("mov.b64 {%0, %1}, %2;" : "=f"(v.z), "=f"(v.w) : "l"(acc2[r][1]));
            __half2 p01 = __floats2half2_rn(v.x, v.y);
            __half2 p23 = __floats2half2_rn(v.z, v.w);
            uint2 u;
            u.x = *reinterpret_cast<unsigned*>(&p01);
            u.y = *reinterpret_cast<unsigned*>(&p23);
            *(uint2*)&g_hW[(long long)row * D + cg * 4] = u;
        }
    }
}

// ---------------------------------------------------------------------------
// K2: SpMM on fp16 hW + bias + relu -> d_out (fp32).
// Persistent warps; each warp owns rows (stride = total warps). Two edges per
// warp-iteration: lanes 0-15 process edge i, lanes 16-31 edge i+1; each lane
// owns 8 features (one 16B uint4 gather = 4 half2). Accumulate with packed
// fma.rn.f32x2; merge half-warps with one shfl_xor(16) + packed add per
// accumulator at row end. 32-bit index math. Unroll x4 = 8 edges in flight.
// ---------------------------------------------------------------------------
__device__ __forceinline__ void accum_edge(
    unsigned long long& a0, unsigned long long& a1,
    unsigned long long& a2, unsigned long long& a3,
    uint4 g, float v)
{
    unsigned long long vv;
    asm("mov.b64 %0, {%1, %1};" : "=l"(vv) : "f"(v));
    float2 f0 = __half22float2(*reinterpret_cast<__half2*>(&g.x));
    float2 f1 = __half22float2(*reinterpret_cast<__half2*>(&g.y));
    float2 f2 = __half22float2(*reinterpret_cast<__half2*>(&g.z));
    float2 f3 = __half22float2(*reinterpret_cast<__half2*>(&g.w));
    unsigned long long p0, p1, p2, p3;
    asm("mov.b64 %0, {%1, %2};" : "=l"(p0) : "f"(f0.x), "f"(f0.y));
    asm("mov.b64 %0, {%1, %2};" : "=l"(p1) : "f"(f1.x), "f"(f1.y));
    asm("mov.b64 %0, {%1, %2};" : "=l"(p2) : "f"(f2.x), "f"(f2.y));
    asm("mov.b64 %0, {%1, %2};" : "=l"(p3) : "f"(f3.x), "f"(f3.y));
    asm("fma.rn.f32x2 %0, %1, %2, %0;" : "+l"(a0) : "l"(vv), "l"(p0));
    asm("fma.rn.f32x2 %0, %1, %2, %0;" : "+l"(a1) : "l"(vv), "l"(p1));
    asm("fma.rn.f32x2 %0, %1, %2, %0;" : "+l"(a2) : "l"(vv), "l"(p2));
    asm("fma.rn.f32x2 %0, %1, %2, %0;" : "+l"(a3) : "l"(vv), "l"(p3));
}

__global__ void __launch_bounds__(256, 4) k_spmm(
    const int*   __restrict__ edge_cols,
    const float* __restrict__ edge_vals,
    const float* __restrict__ bias,
    float*       __restrict__ out,
    int N)
{
    int lane = threadIdx.x & 31;
    int eh   = lane >> 4;            // which edge of the pair this lane serves
    int fl   = lane & 15;            // feature-lane within half-warp
    int lo   = fl * 8;               // first of this lane's 8 features
    int gw   = (blockIdx.x * blockDim.x + threadIdx.x) >> 5;
    int nw   = (gridDim.x * blockDim.x) >> 5;

    // this lane stores features [lo + eh*4, lo + eh*4 + 4)
    float4 bb = *(const float4*)&bias[lo + eh * 4];

    for (int row = gw; row < N; row += nw) {
        int s = __ldg(&g_row_ptr[row]);
        int e = __ldg(&g_row_ptr[row + 1]);

        unsigned long long a0 = 0ull, a1 = 0ull, a2 = 0ull, a3 = 0ull;

        int i = s;
        // main loop: 8 edges per iteration (4 pairs); all 8 edge-stream loads
        // issued before the 4 gather LDG.128s -> 8 edges of MLP in flight
        for (; i + 8 <= e; i += 8) {
            int c[4]; float v[4];
#pragma unroll
            for (int u = 0; u < 4; u++)
                c[u] = __ldcs(&edge_cols[i + 2 * u + eh]);
#pragma unroll
            for (int u = 0; u < 4; u++)
                v[u] = __ldcs(&edge_vals[i + 2 * u + eh]);
            uint4 g[4];
#pragma unroll
            for (int u = 0; u < 4; u++)
                g[u] = *(const uint4*)&g_hW[c[u] * D + lo];
#pragma unroll
            for (int u = 0; u < 4; u++)
                accum_edge(a0, a1, a2, a3, g[u], v[u]);
        }
        // tail: 2 edges at a time, guarded (c=0 is a safe dummy gather, v=0)
        for (; i < e; i += 2) {
            int idx = i + eh;
            int c = 0; float v = 0.f;
            if (idx < e) {
                c = __ldcs(&edge_cols[idx]);
                v = __ldcs(&edge_vals[idx]);
            }
            uint4 g = *(const uint4*)&g_hW[c * D + lo];
            accum_edge(a0, a1, a2, a3, g, v);
        }

        // merge the two half-warps (both halves end with full sums)
        unsigned long long o;
        o = __shfl_xor_sync(0xffffffffu, a0, 16);
        asm("add.rn.f32x2 %0, %0, %1;" : "+l"(a0) : "l"(o));
        o = __shfl_xor_sync(0xffffffffu, a1, 16);
        asm("add.rn.f32x2 %0, %0, %1;" : "+l"(a1) : "l"(o));
        o = __shfl_xor_sync(0xffffffffu, a2, 16);
        asm("add.rn.f32x2 %0, %0, %1;" : "+l"(a2) : "l"(o));
        o = __shfl_xor_sync(0xffffffffu, a3, 16);
        asm("add.rn.f32x2 %0, %0, %1;" : "+l"(a3) : "l"(o));

        // lanes 0-15 store features [lo, lo+4) from a0,a1; lanes 16-31 store
        // [lo+4, lo+8) from a2,a3 — together one coalesced 512B row write.
        unsigned long long sa = eh ? a2 : a0;
        unsigned long long sb = eh ? a3 : a1;
        float2 fa, fb;
        asm("mov.b64 {%0, %1}, %2;" : "=f"(fa.x), "=f"(fa.y) : "l"(sa));
        asm("mov.b64 {%0, %1}, %2;" : "=f"(fb.x), "=f"(fb.y) : "l"(sb));
        float4 r;
        r.x = fmaxf(fa.x + bb.x, 0.f);
        r.y = fmaxf(fa.y + bb.y, 0.f);
        r.z = fmaxf(fb.x + bb.z, 0.f);
        r.w = fmaxf(fb.y + bb.w, 0.f);
        *(float4*)&out[row * D + lo + eh * 4] = r;
    }
}

// ---------------------------------------------------------------------------
// Launch
// Inputs (metadata order): edge_rows[i32 E], edge_cols[i32 E], edge_vals[f32 E],
//                          h[f32 N*128], W[f32 128*128], b[f32 128]
// Output: f32 N*128
// ---------------------------------------------------------------------------
extern "C" void kernel_launch(void* const* d_in, const int* in_sizes, int n_in,
                              void* d_out, int out_size) {
    const int*   edge_rows = (const int*)d_in[0];
    const int*   edge_cols = (const int*)d_in[1];
    const float* edge_vals = (const float*)d_in[2];
    const float* h         = (const float*)d_in[3];
    const float* W         = (const float*)d_in[4];
    const float* b         = (const float*)d_in[5];
    float*       out       = (float*)d_out;

    int E = in_sizes[0];
    int N = in_sizes[3] / D;

    k_transpose_W<<<(D * D + 255) / 256, 256>>>(W);
    k_rowptr<<<(E + 255) / 256, 256>>>(edge_rows, N, E);
    k_gemm_hW<<<(N + 63) / 64, 256>>>(h, N);
    // 1184 blocks: residency still capped at 4/SM by launch_bounds; finer
    // row-stride granularity smooths degree-variance imbalance.
    k_spmm<<<1184, 256>>>(edge_cols, edge_vals, b, out, N);
}